// round 5
// baseline (speedup 1.0000x reference)
#include <cuda_runtime.h>
#include <cuda_bf16.h>
#include <math.h>
#include <stdint.h>

#define BATCH 32
#define DIMQ  64
#define NPROM 4
#define DD    1024
#define EE    768
#define VCV   32000
#define MM    (BATCH*DIMQ)   // 2048
#define TOPK  2
#define NCAND 16
#define EPSV  1e-8f

// -------- scratch --------
__device__ float          g_T[(size_t)VCV * DD];
__device__ __nv_bfloat16  g_Tb[(size_t)VCV * DD];
__device__ float          g_scores[(size_t)MM * VCV];
__device__ float          g_s[(size_t)MM * DD];
__device__ __nv_bfloat16  g_sb[(size_t)MM * DD];
__device__ __nv_bfloat16  g_fwh[(size_t)VCV * EE];
__device__ __nv_bfloat16  g_fwl[(size_t)VCV * EE];
__device__ __nv_bfloat16  g_weh[(size_t)DD * EE];
__device__ __nv_bfloat16  g_wel[(size_t)DD * EE];
__device__ float g_wn[VCV];
__device__ float g_pn[MM];
__device__ int   g_candi[MM * NCAND];
__device__ float g_topv[MM * TOPK];
__device__ int   g_topi[MM * TOPK];

// ---------------- helpers ----------------
__device__ __forceinline__ void cp_async16(void* smem, const void* gmem)
{
    uint32_t s = (uint32_t)__cvta_generic_to_shared(smem);
    asm volatile("cp.async.cg.shared.global [%0], [%1], 16;\n" :: "r"(s), "l"(gmem));
}
__device__ __forceinline__ void cp_commit()
{
    asm volatile("cp.async.commit_group;\n" ::);
}
template<int N>
__device__ __forceinline__ void cp_wait()
{
    asm volatile("cp.async.wait_group %0;\n" :: "n"(N));
}

__device__ __forceinline__ void mma16816(float d[4], const uint32_t a[4], const uint32_t b[2])
{
    asm volatile(
        "mma.sync.aligned.m16n8k16.row.col.f32.bf16.bf16.f32 "
        "{%0,%1,%2,%3}, {%4,%5,%6,%7}, {%8,%9}, {%0,%1,%2,%3};"
        : "+f"(d[0]), "+f"(d[1]), "+f"(d[2]), "+f"(d[3])
        : "r"(a[0]), "r"(a[1]), "r"(a[2]), "r"(a[3]), "r"(b[0]), "r"(b[1]));
}

__device__ __forceinline__ void ldsm_x4(uint32_t& r0, uint32_t& r1, uint32_t& r2, uint32_t& r3,
                                        uint32_t addr)
{
    asm volatile("ldmatrix.sync.aligned.m8n8.x4.shared.b16 {%0,%1,%2,%3}, [%4];"
                 : "=r"(r0), "=r"(r1), "=r"(r2), "=r"(r3) : "r"(addr));
}

__global__ __launch_bounds__(256) void split_kernel(const float* __restrict__ in,
                                                    __nv_bfloat16* __restrict__ hi,
                                                    __nv_bfloat16* __restrict__ lo,
                                                    int n)
{
    int i = blockIdx.x * 256 + threadIdx.x;
    if (i >= n) return;
    float x = in[i];
    __nv_bfloat16 h = __float2bfloat16(x);
    hi[i] = h;
    lo[i] = __float2bfloat16(x - __bfloat162float(h));
}

// ---- MMA tile geometry: 128(m) x 256(n) x 32(k), 3-stage pipeline ----
#define BKT     32
#define PADT    8
#define LDST    (BKT + PADT)            // 40 bf16 per row
#define BMT     128
#define BNT     256
#define NSTG    3
#define A_STAGE (BMT * LDST)            // elements per A stage
#define B_STAGE (BNT * LDST)            // elements per B stage
#define SMEM_ELEMS (NSTG * (A_STAGE + B_STAGE))
#define SMEM_BYTES (SMEM_ELEMS * 2)

// =================================================================
// Shared MMA core. KARG: A/B source resolved by caller via lambda-free
// approach: we duplicate the two kernels (T and scores) since their
// tile-source logic differs.
// =================================================================

__global__ __launch_bounds__(256, 1) void mma_T_kernel(const float* __restrict__ fe_b)
{
    extern __shared__ __nv_bfloat16 smem[];
    __nv_bfloat16* Asm = smem;                    // [NSTG][128][LDST]
    __nv_bfloat16* Bsm = smem + NSTG * A_STAGE;   // [NSTG][256][LDST]

    const int tid    = threadIdx.x;
    const int lane   = tid & 31;
    const int warp   = tid >> 5;
    const int warp_m = warp >> 2;       // 0..1
    const int warp_n = warp & 3;        // 0..3
    const int gid    = lane >> 2;
    const int tig    = lane & 3;
    const int m0 = blockIdx.y * BMT;    // v
    const int n0 = blockIdx.x * BNT;    // d

    // ldmatrix per-lane base offsets (within one stage)
    const int aRow = warp_m * 64 + (lane & 15);
    const int aCol = (lane >> 4) * 8;
    const int bRow = warp_n * 64 + (lane & 7) + ((lane >> 4) << 3);
    const int bCol = ((lane >> 3) & 1) * 8;
    const uint32_t sA = (uint32_t)__cvta_generic_to_shared(Asm);
    const uint32_t sB = (uint32_t)__cvta_generic_to_shared(Bsm);
    const uint32_t aBase = sA + (uint32_t)(aRow * LDST + aCol) * 2;
    const uint32_t bBase = sB + (uint32_t)(bRow * LDST + bCol) * 2;

    float acc[4][8][4];
    #pragma unroll
    for (int mi = 0; mi < 4; mi++)
        #pragma unroll
        for (int nj = 0; nj < 8; nj++)
            #pragma unroll
            for (int q = 0; q < 4; q++) acc[mi][nj][q] = 0.f;

    const int NT = 72;  // 3 passes x 24 k-tiles
    auto load_tile = [&](int t, int stage) {
        const int pass = t / 24;
        const int kk   = (t % 24) * BKT;
        const __nv_bfloat16* Ap = (pass < 2) ? g_fwh : g_fwl;
        const __nv_bfloat16* Bp = (pass == 1) ? g_wel : g_weh;
        // A: 512 chunks (128 rows x 4 segs); i = 0,1
        #pragma unroll
        for (int i = 0; i < 2; i++) {
            int c = tid + i * 256;
            int r = c >> 2, s = (c & 3) * 8;
            cp_async16(Asm + stage * A_STAGE + r * LDST + s,
                       Ap + (size_t)(m0 + r) * EE + kk + s);
        }
        // B: 1024 chunks (256 rows x 4 segs); i = 0..3
        #pragma unroll
        for (int i = 0; i < 4; i++) {
            int c = tid + i * 256;
            int r = c >> 2, s = (c & 3) * 8;
            cp_async16(Bsm + stage * B_STAGE + r * LDST + s,
                       Bp + (size_t)(n0 + r) * EE + kk + s);
        }
        cp_commit();
    };

    load_tile(0, 0);
    load_tile(1, 1);
    for (int t = 0; t < NT; t++) {
        cp_wait<1>();
        __syncthreads();
        if (t + 2 < NT) load_tile(t + 2, (t + 2) % NSTG);

        const int stage = t % NSTG;
        const uint32_t aB = aBase + (uint32_t)(stage * A_STAGE) * 2;
        const uint32_t bB = bBase + (uint32_t)(stage * B_STAGE) * 2;
        #pragma unroll
        for (int ks = 0; ks < 2; ks++) {
            const uint32_t kOff = (uint32_t)(ks * 16) * 2;
            uint32_t a[4][4];
            uint32_t b[8][2];
            #pragma unroll
            for (int mi = 0; mi < 4; mi++)
                ldsm_x4(a[mi][0], a[mi][1], a[mi][2], a[mi][3],
                        aB + (uint32_t)(mi * 16 * LDST) * 2 + kOff);
            #pragma unroll
            for (int njp = 0; njp < 4; njp++)
                ldsm_x4(b[njp * 2][0], b[njp * 2][1], b[njp * 2 + 1][0], b[njp * 2 + 1][1],
                        bB + (uint32_t)(njp * 16 * LDST) * 2 + kOff);
            #pragma unroll
            for (int mi = 0; mi < 4; mi++)
                #pragma unroll
                for (int nj = 0; nj < 8; nj++)
                    mma16816(acc[mi][nj], a[mi], b[nj]);
        }
        __syncthreads();
    }

    #pragma unroll
    for (int mi = 0; mi < 4; mi++) {
        const int gm0 = m0 + warp_m * 64 + mi * 16 + gid;
        const float b0 = fe_b[gm0];
        const float b1 = fe_b[gm0 + 8];
        #pragma unroll
        for (int nj = 0; nj < 8; nj++) {
            const int gn = n0 + warp_n * 64 + nj * 8 + tig * 2;
            float* o0 = g_T + (size_t)gm0 * DD + gn;
            float* o1 = g_T + (size_t)(gm0 + 8) * DD + gn;
            o0[0] = acc[mi][nj][0] + b0;
            o0[1] = acc[mi][nj][1] + b0;
            o1[0] = acc[mi][nj][2] + b1;
            o1[1] = acc[mi][nj][3] + b1;
        }
    }
}

__global__ __launch_bounds__(256, 1) void mma_scores_kernel()
{
    extern __shared__ __nv_bfloat16 smem[];
    __nv_bfloat16* Asm = smem;
    __nv_bfloat16* Bsm = smem + NSTG * A_STAGE;

    const int tid    = threadIdx.x;
    const int lane   = tid & 31;
    const int warp   = tid >> 5;
    const int warp_m = warp >> 2;
    const int warp_n = warp & 3;
    const int gid    = lane >> 2;
    const int tig    = lane & 3;
    const int m0 = blockIdx.y * BMT;
    const int n0 = blockIdx.x * BNT;

    const int aRow = warp_m * 64 + (lane & 15);
    const int aCol = (lane >> 4) * 8;
    const int bRow = warp_n * 64 + (lane & 7) + ((lane >> 4) << 3);
    const int bCol = ((lane >> 3) & 1) * 8;
    const uint32_t sA = (uint32_t)__cvta_generic_to_shared(Asm);
    const uint32_t sB = (uint32_t)__cvta_generic_to_shared(Bsm);
    const uint32_t aBase = sA + (uint32_t)(aRow * LDST + aCol) * 2;
    const uint32_t bBase = sB + (uint32_t)(bRow * LDST + bCol) * 2;

    float acc[4][8][4];
    #pragma unroll
    for (int mi = 0; mi < 4; mi++)
        #pragma unroll
        for (int nj = 0; nj < 8; nj++)
            #pragma unroll
            for (int q = 0; q < 4; q++) acc[mi][nj][q] = 0.f;

    const int NT = DD / BKT;  // 32
    auto load_tile = [&](int t, int stage) {
        const int kk = t * BKT;
        #pragma unroll
        for (int i = 0; i < 2; i++) {
            int c = tid + i * 256;
            int r = c >> 2, s = (c & 3) * 8;
            cp_async16(Asm + stage * A_STAGE + r * LDST + s,
                       g_sb + (size_t)(m0 + r) * DD + kk + s);
        }
        #pragma unroll
        for (int i = 0; i < 4; i++) {
            int c = tid + i * 256;
            int r = c >> 2, s = (c & 3) * 8;
            cp_async16(Bsm + stage * B_STAGE + r * LDST + s,
                       g_Tb + (size_t)(n0 + r) * DD + kk + s);
        }
        cp_commit();
    };

    load_tile(0, 0);
    load_tile(1, 1);
    for (int t = 0; t < NT; t++) {
        cp_wait<1>();
        __syncthreads();
        if (t + 2 < NT) load_tile(t + 2, (t + 2) % NSTG);

        const int stage = t % NSTG;
        const uint32_t aB = aBase + (uint32_t)(stage * A_STAGE) * 2;
        const uint32_t bB = bBase + (uint32_t)(stage * B_STAGE) * 2;
        #pragma unroll
        for (int ks = 0; ks < 2; ks++) {
            const uint32_t kOff = (uint32_t)(ks * 16) * 2;
            uint32_t a[4][4];
            uint32_t b[8][2];
            #pragma unroll
            for (int mi = 0; mi < 4; mi++)
                ldsm_x4(a[mi][0], a[mi][1], a[mi][2], a[mi][3],
                        aB + (uint32_t)(mi * 16 * LDST) * 2 + kOff);
            #pragma unroll
            for (int njp = 0; njp < 4; njp++)
                ldsm_x4(b[njp * 2][0], b[njp * 2][1], b[njp * 2 + 1][0], b[njp * 2 + 1][1],
                        bB + (uint32_t)(njp * 16 * LDST) * 2 + kOff);
            #pragma unroll
            for (int mi = 0; mi < 4; mi++)
                #pragma unroll
                for (int nj = 0; nj < 8; nj++)
                    mma16816(acc[mi][nj], a[mi], b[nj]);
        }
        __syncthreads();
    }

    #pragma unroll
    for (int mi = 0; mi < 4; mi++) {
        const int gm0 = m0 + warp_m * 64 + mi * 16 + gid;
        #pragma unroll
        for (int nj = 0; nj < 8; nj++) {
            const int gn = n0 + warp_n * 64 + nj * 8 + tig * 2;
            float* o0 = g_scores + (size_t)gm0 * VCV + gn;
            float* o1 = g_scores + (size_t)(gm0 + 8) * VCV + gn;
            o0[0] = acc[mi][nj][0];
            o0[1] = acc[mi][nj][1];
            o1[0] = acc[mi][nj][2];
            o1[1] = acc[mi][nj][3];
        }
    }
}

// wn[v] = max(2*||T[v,:]||, EPS); Tb = bf16(T/wn)
__global__ __launch_bounds__(256) void wnorm_kernel()
{
    const int v = blockIdx.x;
    const float* row = g_T + (size_t)v * DD;
    float xs[4];
    float ss = 0.f;
    #pragma unroll
    for (int i = 0; i < 4; i++) {
        xs[i] = row[threadIdx.x + i * 256];
        ss += xs[i] * xs[i];
    }
    __shared__ float red[256];
    red[threadIdx.x] = ss;
    __syncthreads();
    for (int o = 128; o > 0; o >>= 1) {
        if (threadIdx.x < o) red[threadIdx.x] += red[threadIdx.x + o];
        __syncthreads();
    }
    if (threadIdx.x == 0) red[0] = fmaxf(2.0f * sqrtf(red[0]), EPSV);
    __syncthreads();
    const float wn = red[0];
    if (threadIdx.x == 0) g_wn[v] = wn;
    const float inv = 1.0f / wn;
    __nv_bfloat16* trow = g_Tb + (size_t)v * DD;
    #pragma unroll
    for (int i = 0; i < 4; i++)
        trow[threadIdx.x + i * 256] = __float2bfloat16(xs[i] * inv);
}

__global__ __launch_bounds__(256) void s_pnorm_kernel(const float* __restrict__ P)
{
    const int m = blockIdx.x;
    const float* base = P + (size_t)m * NPROM * DD;
    float ss = 0.f;
    #pragma unroll
    for (int i = 0; i < 4; i++) {
        int d = threadIdx.x + i * 256;
        float a = base[d];
        float b = base[DD + d];
        float c = base[2 * DD + d];
        float e = base[3 * DD + d];
        float sum = (a + b) + (c + e);
        g_s[(size_t)m * DD + d]  = sum;
        g_sb[(size_t)m * DD + d] = __float2bfloat16(sum);
        ss += a * a + b * b + c * c + e * e;
    }
    __shared__ float red[256];
    red[threadIdx.x] = ss;
    __syncthreads();
    for (int o = 128; o > 0; o >>= 1) {
        if (threadIdx.x < o) red[threadIdx.x] += red[threadIdx.x + o];
        __syncthreads();
    }
    if (threadIdx.x == 0)
        g_pn[m] = fmaxf(sqrtf(red[0]), EPSV);
}

// top-16 candidates per row
__global__ __launch_bounds__(256) void top16_kernel()
{
    const int m   = blockIdx.x;
    const int tid = threadIdx.x;
    const int lane = tid & 31, warp = tid >> 5;
    const float4* row = (const float4*)(g_scores + (size_t)m * VCV);

    float lv[8];
    int   li[8];
    #pragma unroll
    for (int j = 0; j < 8; j++) { lv[j] = -INFINITY; li[j] = 0x7fffffff; }

    for (int i = tid; i < VCV / 4; i += 256) {
        float4 x4 = row[i];
        const int base = i * 4;
        float xs[4] = {x4.x, x4.y, x4.z, x4.w};
        #pragma unroll
        for (int e = 0; e < 4; e++) {
            float x = xs[e];
            if (x > lv[7]) {
                int v = base + e;
                bool placed = false;
                #pragma unroll
                for (int j = 7; j >= 1; --j) {
                    if (!placed) {
                        if (x > lv[j - 1]) { lv[j] = lv[j - 1]; li[j] = li[j - 1]; }
                        else               { lv[j] = x; li[j] = v; placed = true; }
                    }
                }
                if (!placed) { lv[0] = x; li[0] = v; }
            }
        }
    }

    __shared__ float shv[2048];
    __shared__ int   shi[2048];
    __shared__ float wv[8];
    __shared__ int   wi[8], ws[8];
    #pragma unroll
    for (int j = 0; j < 8; j++) {
        shv[tid * 8 + j] = lv[j];
        shi[tid * 8 + j] = li[j];
    }
    __syncthreads();

    for (int r = 0; r < NCAND; r++) {
        float bv = -INFINITY; int bi = 0x7fffffff; int bs = -1;
        #pragma unroll
        for (int j = 0; j < 8; j++) {
            int t = tid * 8 + j;
            float xv = shv[t];
            int   xi = shi[t];
            if (xv > bv || (xv == bv && xi < bi)) { bv = xv; bi = xi; bs = t; }
        }
        #pragma unroll
        for (int o = 16; o > 0; o >>= 1) {
            float xv = __shfl_down_sync(0xffffffffu, bv, o);
            int   xi = __shfl_down_sync(0xffffffffu, bi, o);
            int   xs = __shfl_down_sync(0xffffffffu, bs, o);
            if (xv > bv || (xv == bv && xi < bi)) { bv = xv; bi = xi; bs = xs; }
        }
        if (lane == 0) { wv[warp] = bv; wi[warp] = bi; ws[warp] = bs; }
        __syncthreads();
        if (tid == 0) {
            float fv = -INFINITY; int fi = 0x7fffffff; int fs = -1;
            #pragma unroll
            for (int w = 0; w < 8; w++) {
                if (wv[w] > fv || (wv[w] == fv && wi[w] < fi)) {
                    fv = wv[w]; fi = wi[w]; fs = ws[w];
                }
            }
            g_candi[m * NCAND + r] = fi;
            shv[fs] = -INFINITY;
        }
        __syncthreads();
    }
}

// exact rescore + select top-2
__global__ __launch_bounds__(256) void rescore_select_kernel()
{
    const int m   = blockIdx.x;
    const int tid = threadIdx.x;
    const int lane = tid & 31, warp = tid >> 5;
    __shared__ float ssh[DD];
    __shared__ float cv[NCAND];
    __shared__ int   ci[NCAND];

    *(float4*)&ssh[tid * 4] = *(const float4*)(g_s + (size_t)m * DD + tid * 4);
    __syncthreads();

    const float pn = g_pn[m];
    for (int c = warp; c < NCAND; c += 8) {
        const int v = g_candi[m * NCAND + c];
        const float4* trow = (const float4*)(g_T + (size_t)v * DD);
        float acc = 0.f;
        #pragma unroll
        for (int i = 0; i < 8; i++) {
            int idx = lane + i * 32;
            float4 t4 = trow[idx];
            float4 s4 = *(const float4*)&ssh[idx * 4];
            acc += t4.x * s4.x + t4.y * s4.y + t4.z * s4.z + t4.w * s4.w;
        }
        #pragma unroll
        for (int o = 16; o > 0; o >>= 1)
            acc += __shfl_down_sync(0xffffffffu, acc, o);
        if (lane == 0) {
            cv[c] = acc / (g_wn[v] * pn);
            ci[c] = v;
        }
    }
    __syncthreads();
    if (tid == 0) {
        float b1 = -INFINITY, b2 = -INFINITY;
        int j1 = 0x7fffffff, j2 = 0x7fffffff;
        #pragma unroll
        for (int c = 0; c < NCAND; c++) {
            float x = cv[c]; int ix = ci[c];
            if (x > b1 || (x == b1 && ix < j1)) { b2 = b1; j2 = j1; b1 = x; j1 = ix; }
            else if (x > b2 || (x == b2 && ix < j2)) { b2 = x; j2 = ix; }
        }
        g_topv[m * 2] = b1;  g_topi[m * 2] = j1;
        g_topv[m * 2 + 1] = b2;  g_topi[m * 2 + 1] = j2;
    }
}

__global__ __launch_bounds__(256) void output_kernel(const float* __restrict__ P,
                                                     float* __restrict__ out)
{
    const int m = blockIdx.x;
    const int r = blockIdx.y;
    float* Zrow = out + ((size_t)m * (NPROM + TOPK) + r) * DD;
    const float* src;
    if (r < TOPK) src = g_T + (size_t)g_topi[m * 2 + r] * DD;
    else          src = P + ((size_t)m * NPROM + (r - TOPK)) * DD;
    const int d = threadIdx.x * 4;
    *(float4*)(Zrow + d) = *(const float4*)(src + d);
    if (r == 0 && threadIdx.x < TOPK) {
        out[(size_t)MM * (NPROM + TOPK) * DD + m * TOPK + threadIdx.x] =
            g_topv[m * TOPK + threadIdx.x];
    }
}

static void* sym_addr(const void* sym)
{
    void* p = nullptr;
    cudaGetSymbolAddress(&p, sym);
    return p;
}

extern "C" void kernel_launch(void* const* d_in, const int* in_sizes, int n_in,
                              void* d_out, int out_size)
{
    const float* P    = (const float*)d_in[0];
    const float* we   = (const float*)d_in[1];
    const float* fe_w = (const float*)d_in[2];
    const float* fe_b = (const float*)d_in[3];
    float* out = (float*)d_out;

    __nv_bfloat16* fwh = (__nv_bfloat16*)sym_addr(g_fwh);
    __nv_bfloat16* fwl = (__nv_bfloat16*)sym_addr(g_fwl);
    __nv_bfloat16* weh = (__nv_bfloat16*)sym_addr(g_weh);
    __nv_bfloat16* wel = (__nv_bfloat16*)sym_addr(g_wel);

    static bool attr_done = false;
    if (!attr_done) {
        cudaFuncSetAttribute(mma_T_kernel,
                             cudaFuncAttributeMaxDynamicSharedMemorySize, SMEM_BYTES);
        cudaFuncSetAttribute(mma_scores_kernel,
                             cudaFuncAttributeMaxDynamicSharedMemorySize, SMEM_BYTES);
        attr_done = true;
    }

    split_kernel<<<(VCV * EE + 255) / 256, 256>>>(fe_w, fwh, fwl, VCV * EE);
    split_kernel<<<(DD * EE + 255) / 256, 256>>>(we, weh, wel, DD * EE);

    {
        dim3 grid(DD / BNT, VCV / BMT);   // 4 x 250
        mma_T_kernel<<<grid, 256, SMEM_BYTES>>>(fe_b);
    }
    wnorm_kernel<<<VCV, 256>>>();
    s_pnorm_kernel<<<MM, 256>>>(P);
    {
        dim3 grid(VCV / BNT, MM / BMT);   // 125 x 16
        mma_scores_kernel<<<grid, 256, SMEM_BYTES>>>();
    }
    top16_kernel<<<MM, 256>>>();
    rescore_select_kernel<<<MM, 256>>>();
    {
        dim3 grid(MM, NPROM + TOPK);
        output_kernel<<<grid, 256>>>(P, out);
    }
    (void)in_sizes; (void)n_in; (void)out_size;
}

// round 6
// speedup vs baseline: 1.0913x; 1.0913x over previous
#include <cuda_runtime.h>
#include <cuda_bf16.h>
#include <math.h>
#include <stdint.h>

#define BATCH 32
#define DIMQ  64
#define NPROM 4
#define DD    1024
#define EE    768
#define VCV   32000
#define MM    (BATCH*DIMQ)   // 2048
#define TOPK  2
#define NCAND 16
#define EPSV  1e-8f

// -------- scratch --------
__device__ float          g_T[(size_t)VCV * DD];
__device__ float          g_scores[(size_t)MM * VCV];
__device__ float          g_s[(size_t)MM * DD];
__device__ __nv_bfloat16  g_sh[(size_t)MM * DD];
__device__ __nv_bfloat16  g_sl[(size_t)MM * DD];
__device__ __nv_bfloat16  g_fwh[(size_t)VCV * EE];
__device__ __nv_bfloat16  g_fwl[(size_t)VCV * EE];
__device__ __nv_bfloat16  g_weh[(size_t)DD * EE];
__device__ __nv_bfloat16  g_wel[(size_t)DD * EE];
__device__ __nv_bfloat16  g_weTh[(size_t)EE * DD];   // we^T hi
__device__ __nv_bfloat16  g_weTl[(size_t)EE * DD];   // we^T lo
__device__ __nv_bfloat16  g_ub[(size_t)MM * EE];     // bf16(u), u = s @ we
__device__ float g_wn[VCV];
__device__ float g_invwn[VCV];
__device__ float g_pn[MM];
__device__ float g_S[MM];                            // row sums of s
__device__ int   g_candi[MM * NCAND];
__device__ float g_topv[MM * TOPK];
__device__ int   g_topi[MM * TOPK];

// ---------------- helpers ----------------
__device__ __forceinline__ void cp_async16(void* smem, const void* gmem)
{
    uint32_t s = (uint32_t)__cvta_generic_to_shared(smem);
    asm volatile("cp.async.cg.shared.global [%0], [%1], 16;\n" :: "r"(s), "l"(gmem));
}
__device__ __forceinline__ void cp_commit()
{
    asm volatile("cp.async.commit_group;\n" ::);
}
template<int N>
__device__ __forceinline__ void cp_wait()
{
    asm volatile("cp.async.wait_group %0;\n" :: "n"(N));
}

__device__ __forceinline__ void mma16816(float d[4], const uint32_t a[4], const uint32_t b[2])
{
    asm volatile(
        "mma.sync.aligned.m16n8k16.row.col.f32.bf16.bf16.f32 "
        "{%0,%1,%2,%3}, {%4,%5,%6,%7}, {%8,%9}, {%0,%1,%2,%3};"
        : "+f"(d[0]), "+f"(d[1]), "+f"(d[2]), "+f"(d[3])
        : "r"(a[0]), "r"(a[1]), "r"(a[2]), "r"(a[3]), "r"(b[0]), "r"(b[1]));
}

__device__ __forceinline__ void ldsm_x4(uint32_t& r0, uint32_t& r1, uint32_t& r2, uint32_t& r3,
                                        uint32_t addr)
{
    asm volatile("ldmatrix.sync.aligned.m8n8.x4.shared.b16 {%0,%1,%2,%3}, [%4];"
                 : "=r"(r0), "=r"(r1), "=r"(r2), "=r"(r3) : "r"(addr));
}

__global__ __launch_bounds__(256) void split_kernel(const float* __restrict__ in,
                                                    __nv_bfloat16* __restrict__ hi,
                                                    __nv_bfloat16* __restrict__ lo,
                                                    int n)
{
    int i = blockIdx.x * 256 + threadIdx.x;
    if (i >= n) return;
    float x = in[i];
    __nv_bfloat16 h = __float2bfloat16(x);
    hi[i] = h;
    lo[i] = __float2bfloat16(x - __bfloat162float(h));
}

// transpose we [DD, EE] -> weT [EE, DD], split into hi/lo bf16
__global__ void trans_split_kernel(const float* __restrict__ we)
{
    __shared__ float tile[32][33];
    const int e0 = blockIdx.x * 32;
    const int d0 = blockIdx.y * 32;
    const int tx = threadIdx.x;       // 0..31
    const int ty = threadIdx.y;       // 0..7
    #pragma unroll
    for (int i = 0; i < 32; i += 8)
        tile[ty + i][tx] = we[(size_t)(d0 + ty + i) * EE + e0 + tx];  // tile[d][e]
    __syncthreads();
    #pragma unroll
    for (int i = 0; i < 32; i += 8) {
        float x = tile[tx][ty + i];   // d=tx, e=ty+i
        size_t o = (size_t)(e0 + ty + i) * DD + d0 + tx;
        __nv_bfloat16 h = __float2bfloat16(x);
        g_weTh[o] = h;
        g_weTl[o] = __float2bfloat16(x - __bfloat162float(h));
    }
}

// ---- MMA tile geometry: 128x128x32, 3-stage pipeline ----
#define BKT     32
#define PADT    8
#define LDST    (BKT + PADT)            // 40 bf16 per row
#define NSTG    3
#define TILE_ST (128 * LDST)            // elements per (A or B) stage
#define SMEM_BYTES (NSTG * 2 * TILE_ST * 2)

// fragment-geometry boilerplate shared by all three MMA kernels
#define MMA_PREAMBLE \
    extern __shared__ __nv_bfloat16 smem[]; \
    __nv_bfloat16* Asm = smem; \
    __nv_bfloat16* Bsm = smem + NSTG * TILE_ST; \
    const int tid    = threadIdx.x; \
    const int lane   = tid & 31; \
    const int warp   = tid >> 5; \
    const int warp_m = warp >> 2; \
    const int warp_n = warp & 3; \
    const int gid    = lane >> 2; \
    const int tig    = lane & 3; \
    const int c0 = tid * 2, c1 = tid * 2 + 1; \
    const int r0 = c0 >> 2, s0 = (c0 & 3) * 8; \
    const int r1 = c1 >> 2, s1 = (c1 & 3) * 8; \
    const int aRow = warp_m * 64 + (lane & 15); \
    const int aCol = (lane >> 4) * 8; \
    const int bRow = warp_n * 32 + (lane & 7) + ((lane >> 4) << 3); \
    const int bCol = ((lane >> 3) & 1) * 8; \
    const uint32_t sA = (uint32_t)__cvta_generic_to_shared(Asm); \
    const uint32_t sB = (uint32_t)__cvta_generic_to_shared(Bsm); \
    const uint32_t aBase = sA + (uint32_t)(aRow * LDST + aCol) * 2; \
    const uint32_t bBase = sB + (uint32_t)(bRow * LDST + bCol) * 2; \
    float acc[4][4][4]; \
    _Pragma("unroll") \
    for (int mi = 0; mi < 4; mi++) \
        _Pragma("unroll") \
        for (int nj = 0; nj < 4; nj++) \
            _Pragma("unroll") \
            for (int q = 0; q < 4; q++) acc[mi][nj][q] = 0.f;

#define MMA_COMPUTE_TILE(stage) \
    { \
        const uint32_t aB = aBase + (uint32_t)((stage) * TILE_ST) * 2; \
        const uint32_t bB = bBase + (uint32_t)((stage) * TILE_ST) * 2; \
        _Pragma("unroll") \
        for (int ks = 0; ks < 2; ks++) { \
            const uint32_t kOff = (uint32_t)(ks * 16) * 2; \
            uint32_t a[4][4]; \
            uint32_t b[4][2]; \
            _Pragma("unroll") \
            for (int mi = 0; mi < 4; mi++) \
                ldsm_x4(a[mi][0], a[mi][1], a[mi][2], a[mi][3], \
                        aB + (uint32_t)(mi * 16 * LDST) * 2 + kOff); \
            _Pragma("unroll") \
            for (int njp = 0; njp < 2; njp++) \
                ldsm_x4(b[njp*2][0], b[njp*2][1], b[njp*2+1][0], b[njp*2+1][1], \
                        bB + (uint32_t)(njp * 16 * LDST) * 2 + kOff); \
            _Pragma("unroll") \
            for (int mi = 0; mi < 4; mi++) \
                _Pragma("unroll") \
                for (int nj = 0; nj < 4; nj++) \
                    mma16816(acc[mi][nj], a[mi], b[nj]); \
        } \
    }

// =================================================================
// T GEMM: T[v,d] = sum_e fe_w[v,e]*we[d,e] + b[v]  (3-pass split bf16)
// =================================================================
__global__ __launch_bounds__(256, 2) void mma_T_kernel(const float* __restrict__ fe_b)
{
    MMA_PREAMBLE
    const int m0 = blockIdx.y * 128;   // v
    const int n0 = blockIdx.x * 128;   // d

    const int NT = 72;  // 3 passes x 24 k-tiles
    auto load_tile = [&](int t, int stage) {
        const int pass = t / 24;
        const int kk   = (t % 24) * BKT;
        const __nv_bfloat16* Ap = (pass < 2) ? g_fwh : g_fwl;
        const __nv_bfloat16* Bp = (pass == 1) ? g_wel : g_weh;
        cp_async16(Asm + stage * TILE_ST + r0 * LDST + s0, Ap + (size_t)(m0 + r0) * EE + kk + s0);
        cp_async16(Asm + stage * TILE_ST + r1 * LDST + s1, Ap + (size_t)(m0 + r1) * EE + kk + s1);
        cp_async16(Bsm + stage * TILE_ST + r0 * LDST + s0, Bp + (size_t)(n0 + r0) * EE + kk + s0);
        cp_async16(Bsm + stage * TILE_ST + r1 * LDST + s1, Bp + (size_t)(n0 + r1) * EE + kk + s1);
        cp_commit();
    };

    load_tile(0, 0);
    load_tile(1, 1);
    for (int t = 0; t < NT; t++) {
        cp_wait<1>();
        __syncthreads();
        if (t + 2 < NT) load_tile(t + 2, (t + 2) % NSTG);
        MMA_COMPUTE_TILE(t % NSTG)
    }

    #pragma unroll
    for (int mi = 0; mi < 4; mi++) {
        const int gm0 = m0 + warp_m * 64 + mi * 16 + gid;
        const float b0 = fe_b[gm0];
        const float b1 = fe_b[gm0 + 8];
        #pragma unroll
        for (int nj = 0; nj < 4; nj++) {
            const int gn = n0 + warp_n * 32 + nj * 8 + tig * 2;
            float* o0 = g_T + (size_t)gm0 * DD + gn;
            float* o1 = g_T + (size_t)(gm0 + 8) * DD + gn;
            o0[0] = acc[mi][nj][0] + b0;
            o0[1] = acc[mi][nj][1] + b0;
            o1[0] = acc[mi][nj][2] + b1;
            o1[1] = acc[mi][nj][3] + b1;
        }
    }
}

// =================================================================
// u GEMM: u[m,e] = sum_d s[m,d]*we[d,e]  (3-pass split), out bf16
// =================================================================
__global__ __launch_bounds__(256, 2) void mma_u_kernel()
{
    MMA_PREAMBLE
    const int m0 = blockIdx.y * 128;   // m
    const int n0 = blockIdx.x * 128;   // e

    const int NT = 96;  // 3 passes x 32 k-tiles over DD
    auto load_tile = [&](int t, int stage) {
        const int pass = t / 32;
        const int kk   = (t % 32) * BKT;
        const __nv_bfloat16* Ap = (pass < 2) ? g_sh : g_sl;
        const __nv_bfloat16* Bp = (pass == 1) ? g_weTl : g_weTh;
        cp_async16(Asm + stage * TILE_ST + r0 * LDST + s0, Ap + (size_t)(m0 + r0) * DD + kk + s0);
        cp_async16(Asm + stage * TILE_ST + r1 * LDST + s1, Ap + (size_t)(m0 + r1) * DD + kk + s1);
        cp_async16(Bsm + stage * TILE_ST + r0 * LDST + s0, Bp + (size_t)(n0 + r0) * DD + kk + s0);
        cp_async16(Bsm + stage * TILE_ST + r1 * LDST + s1, Bp + (size_t)(n0 + r1) * DD + kk + s1);
        cp_commit();
    };

    load_tile(0, 0);
    load_tile(1, 1);
    for (int t = 0; t < NT; t++) {
        cp_wait<1>();
        __syncthreads();
        if (t + 2 < NT) load_tile(t + 2, (t + 2) % NSTG);
        MMA_COMPUTE_TILE(t % NSTG)
    }

    #pragma unroll
    for (int mi = 0; mi < 4; mi++) {
        const int gm0 = m0 + warp_m * 64 + mi * 16 + gid;
        #pragma unroll
        for (int nj = 0; nj < 4; nj++) {
            const int gn = n0 + warp_n * 32 + nj * 8 + tig * 2;
            __nv_bfloat16* o0 = g_ub + (size_t)gm0 * EE + gn;
            __nv_bfloat16* o1 = g_ub + (size_t)(gm0 + 8) * EE + gn;
            o0[0] = __float2bfloat16(acc[mi][nj][0]);
            o0[1] = __float2bfloat16(acc[mi][nj][1]);
            o1[0] = __float2bfloat16(acc[mi][nj][2]);
            o1[1] = __float2bfloat16(acc[mi][nj][3]);
        }
    }
}

// =================================================================
// scores[m,v] = (ub[m]·fwh[v] + b[v]*S[m]) * invwn[v]   (K = 768)
// =================================================================
__global__ __launch_bounds__(256, 2) void mma_scores_kernel(const float* __restrict__ fe_b)
{
    MMA_PREAMBLE
    const int m0 = blockIdx.y * 128;   // m
    const int n0 = blockIdx.x * 128;   // v

    const int NT = EE / BKT;  // 24
    auto load_tile = [&](int t, int stage) {
        const int kk = t * BKT;
        cp_async16(Asm + stage * TILE_ST + r0 * LDST + s0, g_ub + (size_t)(m0 + r0) * EE + kk + s0);
        cp_async16(Asm + stage * TILE_ST + r1 * LDST + s1, g_ub + (size_t)(m0 + r1) * EE + kk + s1);
        cp_async16(Bsm + stage * TILE_ST + r0 * LDST + s0, g_fwh + (size_t)(n0 + r0) * EE + kk + s0);
        cp_async16(Bsm + stage * TILE_ST + r1 * LDST + s1, g_fwh + (size_t)(n0 + r1) * EE + kk + s1);
        cp_commit();
    };

    load_tile(0, 0);
    load_tile(1, 1);
    for (int t = 0; t < NT; t++) {
        cp_wait<1>();
        __syncthreads();
        if (t + 2 < NT) load_tile(t + 2, (t + 2) % NSTG);
        MMA_COMPUTE_TILE(t % NSTG)
    }

    #pragma unroll
    for (int mi = 0; mi < 4; mi++) {
        const int gm0 = m0 + warp_m * 64 + mi * 16 + gid;
        const float S0 = g_S[gm0];
        const float S1 = g_S[gm0 + 8];
        #pragma unroll
        for (int nj = 0; nj < 4; nj++) {
            const int gn = n0 + warp_n * 32 + nj * 8 + tig * 2;
            const float iw0 = g_invwn[gn],  iw1 = g_invwn[gn + 1];
            const float bb0 = fe_b[gn],     bb1 = fe_b[gn + 1];
            float* o0 = g_scores + (size_t)gm0 * VCV + gn;
            float* o1 = g_scores + (size_t)(gm0 + 8) * VCV + gn;
            o0[0] = (acc[mi][nj][0] + bb0 * S0) * iw0;
            o0[1] = (acc[mi][nj][1] + bb1 * S0) * iw1;
            o1[0] = (acc[mi][nj][2] + bb0 * S1) * iw0;
            o1[1] = (acc[mi][nj][3] + bb1 * S1) * iw1;
        }
    }
}

// wn[v] = max(2*||T[v,:]||, EPS), invwn = 1/wn
__global__ __launch_bounds__(256) void wnorm_kernel()
{
    const int v = blockIdx.x;
    const float* row = g_T + (size_t)v * DD;
    float ss = 0.f;
    #pragma unroll
    for (int i = 0; i < 4; i++) {
        float x = row[threadIdx.x + i * 256];
        ss += x * x;
    }
    __shared__ float red[256];
    red[threadIdx.x] = ss;
    __syncthreads();
    for (int o = 128; o > 0; o >>= 1) {
        if (threadIdx.x < o) red[threadIdx.x] += red[threadIdx.x + o];
        __syncthreads();
    }
    if (threadIdx.x == 0) {
        float wn = fmaxf(2.0f * sqrtf(red[0]), EPSV);
        g_wn[v] = wn;
        g_invwn[v] = 1.0f / wn;
    }
}

// s, splits of s, row-sum S, p_norm
__global__ __launch_bounds__(256) void s_pnorm_kernel(const float* __restrict__ P)
{
    const int m = blockIdx.x;
    const float* base = P + (size_t)m * NPROM * DD;
    float ss = 0.f, rs = 0.f;
    #pragma unroll
    for (int i = 0; i < 4; i++) {
        int d = threadIdx.x + i * 256;
        float a = base[d];
        float b = base[DD + d];
        float c = base[2 * DD + d];
        float e = base[3 * DD + d];
        float sum = (a + b) + (c + e);
        g_s[(size_t)m * DD + d] = sum;
        __nv_bfloat16 h = __float2bfloat16(sum);
        g_sh[(size_t)m * DD + d] = h;
        g_sl[(size_t)m * DD + d] = __float2bfloat16(sum - __bfloat162float(h));
        ss += a * a + b * b + c * c + e * e;
        rs += sum;
    }
    __shared__ float red[256];
    __shared__ float red2[256];
    red[threadIdx.x] = ss;
    red2[threadIdx.x] = rs;
    __syncthreads();
    for (int o = 128; o > 0; o >>= 1) {
        if (threadIdx.x < o) {
            red[threadIdx.x]  += red[threadIdx.x + o];
            red2[threadIdx.x] += red2[threadIdx.x + o];
        }
        __syncthreads();
    }
    if (threadIdx.x == 0) {
        g_pn[m] = fmaxf(sqrtf(red[0]), EPSV);
        g_S[m]  = red2[0];
    }
}

// top-16 candidates per row
__global__ __launch_bounds__(256) void top16_kernel()
{
    const int m   = blockIdx.x;
    const int tid = threadIdx.x;
    const int lane = tid & 31, warp = tid >> 5;
    const float4* row = (const float4*)(g_scores + (size_t)m * VCV);

    float lv[8];
    int   li[8];
    #pragma unroll
    for (int j = 0; j < 8; j++) { lv[j] = -INFINITY; li[j] = 0x7fffffff; }

    for (int i = tid; i < VCV / 4; i += 256) {
        float4 x4 = row[i];
        const int base = i * 4;
        float xs[4] = {x4.x, x4.y, x4.z, x4.w};
        #pragma unroll
        for (int e = 0; e < 4; e++) {
            float x = xs[e];
            if (x > lv[7]) {
                int v = base + e;
                bool placed = false;
                #pragma unroll
                for (int j = 7; j >= 1; --j) {
                    if (!placed) {
                        if (x > lv[j - 1]) { lv[j] = lv[j - 1]; li[j] = li[j - 1]; }
                        else               { lv[j] = x; li[j] = v; placed = true; }
                    }
                }
                if (!placed) { lv[0] = x; li[0] = v; }
            }
        }
    }

    __shared__ float shv[2048];
    __shared__ int   shi[2048];
    __shared__ float wv[8];
    __shared__ int   wi[8], ws[8];
    #pragma unroll
    for (int j = 0; j < 8; j++) {
        shv[tid * 8 + j] = lv[j];
        shi[tid * 8 + j] = li[j];
    }
    __syncthreads();

    for (int r = 0; r < NCAND; r++) {
        float bv = -INFINITY; int bi = 0x7fffffff; int bs = -1;
        #pragma unroll
        for (int j = 0; j < 8; j++) {
            int t = tid * 8 + j;
            float xv = shv[t];
            int   xi = shi[t];
            if (xv > bv || (xv == bv && xi < bi)) { bv = xv; bi = xi; bs = t; }
        }
        #pragma unroll
        for (int o = 16; o > 0; o >>= 1) {
            float xv = __shfl_down_sync(0xffffffffu, bv, o);
            int   xi = __shfl_down_sync(0xffffffffu, bi, o);
            int   xs = __shfl_down_sync(0xffffffffu, bs, o);
            if (xv > bv || (xv == bv && xi < bi)) { bv = xv; bi = xi; bs = xs; }
        }
        if (lane == 0) { wv[warp] = bv; wi[warp] = bi; ws[warp] = bs; }
        __syncthreads();
        if (tid == 0) {
            float fv = -INFINITY; int fi = 0x7fffffff; int fs = -1;
            #pragma unroll
            for (int w = 0; w < 8; w++) {
                if (wv[w] > fv || (wv[w] == fv && wi[w] < fi)) {
                    fv = wv[w]; fi = wi[w]; fs = ws[w];
                }
            }
            g_candi[m * NCAND + r] = fi;
            shv[fs] = -INFINITY;
        }
        __syncthreads();
    }
}

// exact rescore + select top-2
__global__ __launch_bounds__(256) void rescore_select_kernel()
{
    const int m   = blockIdx.x;
    const int tid = threadIdx.x;
    const int lane = tid & 31, warp = tid >> 5;
    __shared__ float ssh[DD];
    __shared__ float cv[NCAND];
    __shared__ int   ci[NCAND];

    *(float4*)&ssh[tid * 4] = *(const float4*)(g_s + (size_t)m * DD + tid * 4);
    __syncthreads();

    const float pn = g_pn[m];
    for (int c = warp; c < NCAND; c += 8) {
        const int v = g_candi[m * NCAND + c];
        const float4* trow = (const float4*)(g_T + (size_t)v * DD);
        float acc = 0.f;
        #pragma unroll
        for (int i = 0; i < 8; i++) {
            int idx = lane + i * 32;
            float4 t4 = trow[idx];
            float4 s4 = *(const float4*)&ssh[idx * 4];
            acc += t4.x * s4.x + t4.y * s4.y + t4.z * s4.z + t4.w * s4.w;
        }
        #pragma unroll
        for (int o = 16; o > 0; o >>= 1)
            acc += __shfl_down_sync(0xffffffffu, acc, o);
        if (lane == 0) {
            cv[c] = acc / (g_wn[v] * pn);
            ci[c] = v;
        }
    }
    __syncthreads();
    if (tid == 0) {
        float b1 = -INFINITY, b2 = -INFINITY;
        int j1 = 0x7fffffff, j2 = 0x7fffffff;
        #pragma unroll
        for (int c = 0; c < NCAND; c++) {
            float x = cv[c]; int ix = ci[c];
            if (x > b1 || (x == b1 && ix < j1)) { b2 = b1; j2 = j1; b1 = x; j1 = ix; }
            else if (x > b2 || (x == b2 && ix < j2)) { b2 = x; j2 = ix; }
        }
        g_topv[m * 2] = b1;  g_topi[m * 2] = j1;
        g_topv[m * 2 + 1] = b2;  g_topi[m * 2 + 1] = j2;
    }
}

__global__ __launch_bounds__(256) void output_kernel(const float* __restrict__ P,
                                                     float* __restrict__ out)
{
    const int m = blockIdx.x;
    const int r = blockIdx.y;
    float* Zrow = out + ((size_t)m * (NPROM + TOPK) + r) * DD;
    const float* src;
    if (r < TOPK) src = g_T + (size_t)g_topi[m * 2 + r] * DD;
    else          src = P + ((size_t)m * NPROM + (r - TOPK)) * DD;
    const int d = threadIdx.x * 4;
    *(float4*)(Zrow + d) = *(const float4*)(src + d);
    if (r == 0 && threadIdx.x < TOPK) {
        out[(size_t)MM * (NPROM + TOPK) * DD + m * TOPK + threadIdx.x] =
            g_topv[m * TOPK + threadIdx.x];
    }
}

static void* sym_addr(const void* sym)
{
    void* p = nullptr;
    cudaGetSymbolAddress(&p, sym);
    return p;
}

extern "C" void kernel_launch(void* const* d_in, const int* in_sizes, int n_in,
                              void* d_out, int out_size)
{
    const float* P    = (const float*)d_in[0];
    const float* we   = (const float*)d_in[1];
    const float* fe_w = (const float*)d_in[2];
    const float* fe_b = (const float*)d_in[3];
    float* out = (float*)d_out;

    __nv_bfloat16* fwh = (__nv_bfloat16*)sym_addr(g_fwh);
    __nv_bfloat16* fwl = (__nv_bfloat16*)sym_addr(g_fwl);
    __nv_bfloat16* weh = (__nv_bfloat16*)sym_addr(g_weh);
    __nv_bfloat16* wel = (__nv_bfloat16*)sym_addr(g_wel);

    static bool attr_done = false;
    if (!attr_done) {
        cudaFuncSetAttribute(mma_T_kernel,
                             cudaFuncAttributeMaxDynamicSharedMemorySize, SMEM_BYTES);
        cudaFuncSetAttribute(mma_u_kernel,
                             cudaFuncAttributeMaxDynamicSharedMemorySize, SMEM_BYTES);
        cudaFuncSetAttribute(mma_scores_kernel,
                             cudaFuncAttributeMaxDynamicSharedMemorySize, SMEM_BYTES);
        attr_done = true;
    }

    // prep: splits, transpose, s-stats
    split_kernel<<<(VCV * EE + 255) / 256, 256>>>(fe_w, fwh, fwl, VCV * EE);
    split_kernel<<<(DD * EE + 255) / 256, 256>>>(we, weh, wel, DD * EE);
    {
        dim3 grid(EE / 32, DD / 32);
        trans_split_kernel<<<grid, dim3(32, 8)>>>(we);
    }
    s_pnorm_kernel<<<MM, 256>>>(P);

    // u = s @ we  (bf16 out)
    {
        dim3 grid(EE / 128, MM / 128);       // 6 x 16
        mma_u_kernel<<<grid, 256, SMEM_BYTES>>>();
    }
    // T = fe_w @ we^T + b
    {
        dim3 grid(DD / 128, VCV / 128);      // 8 x 250
        mma_T_kernel<<<grid, 256, SMEM_BYTES>>>(fe_b);
    }
    wnorm_kernel<<<VCV, 256>>>();
    // scores = (u @ fe_w^T + b*S) * invwn
    {
        dim3 grid(VCV / 128, MM / 128);      // 250 x 16
        mma_scores_kernel<<<grid, 256, SMEM_BYTES>>>(fe_b);
    }
    top16_kernel<<<MM, 256>>>();
    rescore_select_kernel<<<MM, 256>>>();
    {
        dim3 grid(MM, NPROM + TOPK);
        output_kernel<<<grid, 256>>>(P, out);
    }
    (void)in_sizes; (void)n_in; (void)out_size;
}